// round 9
// baseline (speedup 1.0000x reference)
#include <cuda_runtime.h>
#include <cuda_bf16.h>
#include <math.h>
#include <stdint.h>

#define BATCH   32768
#define ROWS    64
#define NBLK    (BATCH / ROWS)      // 512
#define EMBED   300
#define VOCAB   100000
#define CTXP    304                 // padded bf16 ctx row (608 B, 16B aligned)
#define KNEG    10
#define KPAD    320
#define THREADS 256
#define ROWB    656                 // smem row pitch bytes (328 bf16)
#define BCHUNK  32
#define NCHUNK  10

// ---- smem float-index layout for misc block ----
#define SMF_NLL   0                  // 64
#define SMF_DENO  64                 // 32
#define SMF_WCLS  96                 // 640
#define SMF_BENC  736                // 320
#define SMF_BDEC  1056               // 320
#define SMF_LGP   1376               // 128
#define SMF_LGQ   1504               // 128
// ---- smem byte layout ----
#define SMB_A     6656
#define SMB_A2    (SMB_A  + ROWS * ROWB)      // 48640
#define SMB_B     (SMB_A2 + ROWS * ROWB)      // 90624
#define SM_TOTAL  (SMB_B  + BCHUNK * ROWB)    // 111616 -> 2 blocks/SM

__device__ __nv_bfloat16 g_Wenc[KPAD * KPAD];
__device__ __nv_bfloat16 g_Wdec[KPAD * KPAD];
__device__ __nv_bfloat16 g_ctx[(size_t)VOCAB * CTXP];   // bf16 padded ctx table
__device__ float2 g_partials[NBLK];

__device__ __forceinline__ uint32_t smem_u32(const void* p) {
    uint32_t a;
    asm("{ .reg .u64 t; cvta.to.shared.u64 t, %1; cvt.u32.u64 %0, t; }" : "=r"(a) : "l"(p));
    return a;
}

__device__ __forceinline__ void ldsm_x4(uint32_t* r, uint32_t addr) {
    asm volatile("ldmatrix.sync.aligned.m8n8.x4.shared.b16 {%0,%1,%2,%3}, [%4];"
                 : "=r"(r[0]), "=r"(r[1]), "=r"(r[2]), "=r"(r[3]) : "r"(addr));
}

__device__ __forceinline__ void mma_bf16(float* d, const uint32_t* a, const uint32_t* b) {
    asm volatile("mma.sync.aligned.m16n8k16.row.col.f32.bf16.bf16.f32 "
                 "{%0,%1,%2,%3},{%4,%5,%6,%7},{%8,%9},{%0,%1,%2,%3};"
                 : "+f"(d[0]), "+f"(d[1]), "+f"(d[2]), "+f"(d[3])
                 : "r"(a[0]), "r"(a[1]), "r"(a[2]), "r"(a[3]), "r"(b[0]), "r"(b[1]));
}

__device__ __forceinline__ uint32_t bf2_bits(float lo, float hi) {
    __nv_bfloat162 t = __floats2bfloat162_rn(lo, hi);
    return *(uint32_t*)&t;
}

// ---------------------------------------------------------------------------
// Weight convert: fp32 [300][300] -> bf16 [320][320] zero-padded
// ---------------------------------------------------------------------------
__global__ __launch_bounds__(256) void convert_w(__nv_bfloat16* __restrict__ dst,
                                                 const float* __restrict__ src)
{
    const int idx = blockIdx.x * 256 + threadIdx.x;
    if (idx >= KPAD * KPAD) return;
    const int h = idx / KPAD;
    const int k = idx - h * KPAD;
    dst[idx] = __float2bfloat16((h < 300 && k < 300) ? src[h * 300 + k] : 0.f);
}

// ---------------------------------------------------------------------------
// ctx_emb convert: fp32 [100000][300] -> bf16 [100000][304] zero-padded.
// One thread per 8-col chunk (38 chunks/row). Fully coalesced both sides.
// ---------------------------------------------------------------------------
__global__ __launch_bounds__(256) void convert_ctx(const float* __restrict__ src)
{
    const long long idx = (long long)blockIdx.x * 256 + threadIdx.x;
    if (idx >= (long long)VOCAB * (CTXP / 8)) return;
    const int r  = (int)(idx / (CTXP / 8));
    const int c0 = (int)(idx - (long long)r * (CTXP / 8)) * 8;

    const float* sp = src + (size_t)r * EMBED + c0;
    float4 v0 = make_float4(0.f, 0.f, 0.f, 0.f);
    float4 v1 = make_float4(0.f, 0.f, 0.f, 0.f);
    if (c0 < 296) {             // full 8 valid
        v0 = *(const float4*)sp;
        v1 = *(const float4*)(sp + 4);
    } else if (c0 == 296) {     // 296..299 valid, 300..303 zero
        v0 = *(const float4*)sp;
    }
    uint4 o;
    o.x = bf2_bits(v0.x, v0.y);
    o.y = bf2_bits(v0.z, v0.w);
    o.z = bf2_bits(v1.x, v1.y);
    o.w = bf2_bits(v1.z, v1.w);
    *(uint4*)(g_ctx + (size_t)r * CTXP + c0) = o;
}

__device__ __forceinline__ float dot8(uint4 c, uint4 x)
{
    const float2 c0 = __bfloat1622float2(*(const __nv_bfloat162*)&c.x);
    const float2 c1 = __bfloat1622float2(*(const __nv_bfloat162*)&c.y);
    const float2 c2 = __bfloat1622float2(*(const __nv_bfloat162*)&c.z);
    const float2 c3 = __bfloat1622float2(*(const __nv_bfloat162*)&c.w);
    const float2 x0 = __bfloat1622float2(*(const __nv_bfloat162*)&x.x);
    const float2 x1 = __bfloat1622float2(*(const __nv_bfloat162*)&x.y);
    const float2 x2 = __bfloat1622float2(*(const __nv_bfloat162*)&x.z);
    const float2 x3 = __bfloat1622float2(*(const __nv_bfloat162*)&x.w);
    return c0.x * x0.x + c0.y * x0.y + c1.x * x1.x + c1.y * x1.y
         + c2.x * x2.x + c2.y * x2.y + c3.x * x3.x + c3.y * x3.y;
}

// ---------------------------------------------------------------------------
// Fused main kernel — 256 threads (8 warps), 2 blocks/SM
// ---------------------------------------------------------------------------
__global__ __launch_bounds__(THREADS, 2) void fused_kernel(
    const int* __restrict__ cen_ids,  const int* __restrict__ ctx_ids,
    const int* __restrict__ neg_ids,  const int* __restrict__ labels,
    const float* __restrict__ cen_emb,
    const float* __restrict__ b_enc,  const float* __restrict__ b_dec,
    const float* __restrict__ W_cls,  const float* __restrict__ b_cls)
{
    extern __shared__ char smc[];
    float* smf = (float*)smc;
    const uint32_t sb = smem_u32(smc);
    const int tid  = threadIdx.x;
    const int wid  = tid >> 5;
    const int lane = tid & 31;
    const int r0   = blockIdx.x * ROWS;

    // ---- Phase 0: constants + gather emb -> bf16 A tile ----
    for (int i = tid; i < 640; i += THREADS) {
        const int cls = i / KPAD, col = i - cls * KPAD;
        smf[SMF_WCLS + i] = (col < 300) ? W_cls[cls * 300 + col] : 0.f;
    }
    for (int i = tid; i < KPAD; i += THREADS) {
        smf[SMF_BENC + i] = (i < 300) ? b_enc[i] : 0.f;
        smf[SMF_BDEC + i] = (i < 300) ? b_dec[i] : 0.f;
    }
    for (int idx = tid; idx < ROWS * (KPAD / 2); idx += THREADS) {
        const int r = idx / (KPAD / 2);
        const int c = (idx - r * (KPAD / 2)) * 2;
        float2 v = make_float2(0.f, 0.f);
        if (c < 300)
            v = *(const float2*)(cen_emb + (size_t)cen_ids[r0 + r] * EMBED + c);
        *(uint32_t*)(smc + SMB_A + r * ROWB + c * 2) = bf2_bits(v.x, v.y);
    }
    __syncthreads();

    const int mg    = wid & 3;
    const int nhalf = wid >> 2;
    const int m0    = mg * 16;
    const int rowA  = m0 + (lane >> 2);
    const int cq    = (lane & 3) * 2;
    float lg00 = 0.f, lg01 = 0.f, lg10 = 0.f, lg11 = 0.f;

    // ================= two chained GEMMs =================
    #pragma unroll 1
    for (int g = 0; g < 2; ++g) {
        const __nv_bfloat16* gW = g ? g_Wdec : g_Wenc;
        const uint32_t aBase = sb + (g ? SMB_A2 : SMB_A);
        const uint32_t aAddr0 = aBase + (uint32_t)(m0 + (lane & 15)) * ROWB
                              + (uint32_t)((lane >> 4) * 8) * 2;
        const uint32_t bAddr0 = sb + SMB_B
                              + (uint32_t)(nhalf * 16 + ((lane >> 4) << 3) + (lane & 7)) * ROWB
                              + (uint32_t)(((lane >> 3) & 1) * 8) * 2;

        #pragma unroll 1
        for (int chunk = 0; chunk < NCHUNK; ++chunk) {
            const int n0 = chunk * BCHUNK;
            {
                const uint4* src = (const uint4*)(gW + (size_t)n0 * KPAD);
                for (int i = tid; i < BCHUNK * 20; i += THREADS) {
                    const int r = i / 20, q = (i - r * 20) * 2;
                    *(uint4*)(smc + SMB_B + r * ROWB + q * 16)       = src[r * 40 + q];
                    *(uint4*)(smc + SMB_B + r * ROWB + (q + 1) * 16) = src[r * 40 + q + 1];
                }
            }
            __syncthreads();

            float acc[2][4];
            #pragma unroll
            for (int j = 0; j < 2; ++j)
                #pragma unroll
                for (int i = 0; i < 4; ++i) acc[j][i] = 0.f;

            #pragma unroll 5
            for (int ks = 0; ks < 20; ++ks) {
                uint32_t a[4], b[4];
                ldsm_x4(a, aAddr0 + ks * 32);
                ldsm_x4(b, bAddr0 + ks * 32);
                mma_bf16(acc[0], a, b);
                mma_bf16(acc[1], a, b + 2);
            }

            if (g == 0) {
                #pragma unroll
                for (int j = 0; j < 2; ++j) {
                    const int c0 = n0 + nhalf * 16 + j * 8 + cq;
                    const float be0 = smf[SMF_BENC + c0], be1 = smf[SMF_BENC + c0 + 1];
                    const float v0 = acc[j][0] + be0, v1 = acc[j][1] + be1;
                    const float v2 = acc[j][2] + be0, v3 = acc[j][3] + be1;
                    const float w00 = smf[SMF_WCLS + c0],       w01 = smf[SMF_WCLS + c0 + 1];
                    const float w10 = smf[SMF_WCLS + 320 + c0], w11 = smf[SMF_WCLS + 320 + c0 + 1];
                    lg00 += v0 * w00 + v1 * w01;  lg01 += v0 * w10 + v1 * w11;
                    lg10 += v2 * w00 + v3 * w01;  lg11 += v2 * w10 + v3 * w11;
                    *(uint32_t*)(smc + SMB_A2 + rowA * ROWB + c0 * 2)       = bf2_bits(v0, v1);
                    *(uint32_t*)(smc + SMB_A2 + (rowA + 8) * ROWB + c0 * 2) = bf2_bits(v2, v3);
                }
            } else {
                #pragma unroll
                for (int j = 0; j < 2; ++j) {
                    const int c0 = n0 + nhalf * 16 + j * 8 + cq;
                    const float bd0 = smf[SMF_BDEC + c0], bd1 = smf[SMF_BDEC + c0 + 1];
                    *(uint32_t*)(smc + SMB_A + rowA * ROWB + c0 * 2) =
                        bf2_bits(acc[j][0] + bd0, acc[j][1] + bd1);
                    *(uint32_t*)(smc + SMB_A + (rowA + 8) * ROWB + c0 * 2) =
                        bf2_bits(acc[j][2] + bd0, acc[j][3] + bd1);
                }
            }
            __syncthreads();
        }

        if (g == 0) {
            lg00 += __shfl_xor_sync(0xffffffffu, lg00, 1);
            lg00 += __shfl_xor_sync(0xffffffffu, lg00, 2);
            lg01 += __shfl_xor_sync(0xffffffffu, lg01, 1);
            lg01 += __shfl_xor_sync(0xffffffffu, lg01, 2);
            lg10 += __shfl_xor_sync(0xffffffffu, lg10, 1);
            lg10 += __shfl_xor_sync(0xffffffffu, lg10, 2);
            lg11 += __shfl_xor_sync(0xffffffffu, lg11, 1);
            lg11 += __shfl_xor_sync(0xffffffffu, lg11, 2);
            if ((lane & 3) == 0) {
                const int base = nhalf ? SMF_LGQ : SMF_LGP;
                smf[base + rowA * 2]           = lg00;
                smf[base + rowA * 2 + 1]       = lg01;
                smf[base + (rowA + 8) * 2]     = lg10;
                smf[base + (rowA + 8) * 2 + 1] = lg11;
            }
            __syncthreads();
            if (tid < ROWS) {
                const float l0 = smf[SMF_LGP + tid * 2]     + smf[SMF_LGQ + tid * 2]     + b_cls[0];
                const float l1 = smf[SMF_LGP + tid * 2 + 1] + smf[SMF_LGQ + tid * 2 + 1] + b_cls[1];
                const float m  = fmaxf(l0, l1);
                const float lse = m + log1pf(__expf(fminf(l0, l1) - m));
                smf[SMF_NLL + tid] = lse - (labels[r0 + tid] ? l1 : l0);
            }
        }
    }

    // ---- Phase 3: pos/neg dots vs bf16 ctx table (both sides bf16) ----
    const int o = lane >> 3;
    const int l = lane & 7;
    float accDeno = 0.f;

    #pragma unroll 1
    for (int t = 0; t < 8; ++t) {
        const int r  = wid * 8 + t;
        const int gr = r0 + r;
        const uint4* cv = (const uint4*)(smc + SMB_A + r * ROWB);

        #pragma unroll
        for (int round = 0; round < 3; ++round) {
            const int j = round * 4 + o;
            const bool valid = (j < 11);
            int widx = 0;
            if (valid) widx = (j == 0) ? ctx_ids[gr] : neg_ids[gr * KNEG + (j - 1)];
            const uint4* xp = (const uint4*)(g_ctx + (size_t)widx * CTXP);

            float acc = 0.f;
            #pragma unroll
            for (int s = 0; s < 5; ++s) {
                const int e = s * 8 + l;                 // uint4 index (8 bf16)
                if (e < 38) acc += dot8(cv[e], xp[e]);
            }
            acc += __shfl_down_sync(0xffffffffu, acc, 4, 8);
            acc += __shfl_down_sync(0xffffffffu, acc, 2, 8);
            acc += __shfl_down_sync(0xffffffffu, acc, 1, 8);

            if (l == 0 && valid) {
                const float s1 = fminf(fmaxf(acc, -10.f), 10.f);
                accDeno += (j == 0) ? log1pf(__expf(-s1)) : log1pf(__expf(s1));
            }
        }
    }
    if (l == 0) smf[SMF_DENO + wid * 4 + o] = accDeno;
    __syncthreads();

    if (tid == 0) {
        float sd = 0.f, sn = 0.f;
        #pragma unroll
        for (int i = 0; i < 32; ++i) sd += smf[SMF_DENO + i];
        #pragma unroll
        for (int i = 0; i < ROWS; ++i) sn += smf[SMF_NLL + i];
        g_partials[blockIdx.x] = make_float2(sd, sn);
    }
}

__global__ __launch_bounds__(256) void finalize_kernel(float* __restrict__ out)
{
    __shared__ float sd[256], sn[256];
    const int t = threadIdx.x;
    const float2 p0 = g_partials[t];
    const float2 p1 = g_partials[t + 256];
    sd[t] = p0.x + p1.x;
    sn[t] = p0.y + p1.y;
    __syncthreads();
    for (int ofs = 128; ofs > 0; ofs >>= 1) {
        if (t < ofs) { sd[t] += sd[t + ofs]; sn[t] += sn[t + ofs]; }
        __syncthreads();
    }
    if (t == 0) {
        const float invB = 1.0f / (float)BATCH;
        float deno = fminf(fmaxf(sd[0] * invB, 1e-5f), 10.f);
        float cono = fminf(fmaxf(sn[0] * invB, 1e-5f), 10.f);
        out[0] = fmaxf(deno + cono, 1e-5f);
        out[1] = deno;
        out[2] = cono;
    }
}

extern "C" void kernel_launch(void* const* d_in, const int* in_sizes, int n_in,
                              void* d_out, int out_size)
{
    const int*   cen_ids = (const int*)  d_in[0];
    const int*   ctx_ids = (const int*)  d_in[1];
    const int*   neg_ids = (const int*)  d_in[2];
    const int*   labels  = (const int*)  d_in[3];
    const float* cen_emb = (const float*)d_in[4];
    const float* ctx_emb = (const float*)d_in[5];
    const float* W_enc   = (const float*)d_in[6];
    const float* b_enc   = (const float*)d_in[7];
    const float* W_dec   = (const float*)d_in[8];
    const float* b_dec   = (const float*)d_in[9];
    const float* W_cls   = (const float*)d_in[10];
    const float* b_cls   = (const float*)d_in[11];

    __nv_bfloat16* we;  cudaGetSymbolAddress((void**)&we, g_Wenc);
    __nv_bfloat16* wd;  cudaGetSymbolAddress((void**)&wd, g_Wdec);

    const int cBlocks = (KPAD * KPAD + 255) / 256;
    convert_w<<<cBlocks, 256>>>(we, W_enc);
    convert_w<<<cBlocks, 256>>>(wd, W_dec);

    const long long ctxThreads = (long long)VOCAB * (CTXP / 8);
    convert_ctx<<<(int)((ctxThreads + 255) / 256), 256>>>(ctx_emb);

    cudaFuncSetAttribute(fused_kernel,
                         cudaFuncAttributeMaxDynamicSharedMemorySize, SM_TOTAL);
    fused_kernel<<<NBLK, THREADS, SM_TOTAL>>>(
        cen_ids, ctx_ids, neg_ids, labels, cen_emb,
        b_enc, b_dec, W_cls, b_cls);
    finalize_kernel<<<1, 256>>>((float*)d_out);
}

// round 10
// speedup vs baseline: 1.0926x; 1.0926x over previous
#include <cuda_runtime.h>
#include <cuda_bf16.h>
#include <math.h>
#include <stdint.h>

#define BATCH   32768
#define ROWS    64
#define NBLK    (BATCH / ROWS)      // 512
#define EMBED   300
#define VOCAB   100000
#define CTXP    304                 // padded bf16 row (608 B)
#define KNEG    10
#define KPAD    320
#define THREADS 256
#define ROWB    656                 // smem row pitch bytes (328 bf16)
#define BCHUNK  32
#define NSTEP   20                  // 2 GEMMs x 10 chunks

// ---- smem float-index layout for misc block ----
#define SMF_NLL   0                  // 64
#define SMF_WCLS  96                 // 640
#define SMF_BENC  736                // 320
#define SMF_BDEC  1056               // 320
#define SMF_LGP   1376               // 128
#define SMF_LGQ   1504               // 128
// ---- smem byte layout ----
#define SMB_A     6656
#define SMB_A2    (SMB_A  + ROWS * ROWB)      // 48640
#define SMB_B     (SMB_A2 + ROWS * ROWB)      // 90624
#define SM_TOTAL  (SMB_B  + BCHUNK * ROWB)    // 111616 -> 2 blocks/SM

__device__ __nv_bfloat16 g_Wenc[KPAD * KPAD];
__device__ __nv_bfloat16 g_Wdec[KPAD * KPAD];
__device__ __nv_bfloat16 g_ctx[(size_t)VOCAB * CTXP];
__device__ __nv_bfloat16 g_cv[(size_t)BATCH * CTXP];
__device__ float g_nll[NBLK];
__device__ float g_deno[NBLK];

__device__ __forceinline__ uint32_t smem_u32(const void* p) {
    uint32_t a;
    asm("{ .reg .u64 t; cvta.to.shared.u64 t, %1; cvt.u32.u64 %0, t; }" : "=r"(a) : "l"(p));
    return a;
}

__device__ __forceinline__ void ldsm_x4(uint32_t* r, uint32_t addr) {
    asm volatile("ldmatrix.sync.aligned.m8n8.x4.shared.b16 {%0,%1,%2,%3}, [%4];"
                 : "=r"(r[0]), "=r"(r[1]), "=r"(r[2]), "=r"(r[3]) : "r"(addr));
}

__device__ __forceinline__ void mma_bf16(float* d, const uint32_t* a, const uint32_t* b) {
    asm volatile("mma.sync.aligned.m16n8k16.row.col.f32.bf16.bf16.f32 "
                 "{%0,%1,%2,%3},{%4,%5,%6,%7},{%8,%9},{%0,%1,%2,%3};"
                 : "+f"(d[0]), "+f"(d[1]), "+f"(d[2]), "+f"(d[3])
                 : "r"(a[0]), "r"(a[1]), "r"(a[2]), "r"(a[3]), "r"(b[0]), "r"(b[1]));
}

__device__ __forceinline__ uint32_t bf2_bits(float lo, float hi) {
    __nv_bfloat162 t = __floats2bfloat162_rn(lo, hi);
    return *(uint32_t*)&t;
}

// ---------------------------------------------------------------------------
// Converts
// ---------------------------------------------------------------------------
__global__ __launch_bounds__(256) void convert_w(__nv_bfloat16* __restrict__ dst,
                                                 const float* __restrict__ src)
{
    const int idx = blockIdx.x * 256 + threadIdx.x;
    if (idx >= KPAD * KPAD) return;
    const int h = idx / KPAD;
    const int k = idx - h * KPAD;
    dst[idx] = __float2bfloat16((h < 300 && k < 300) ? src[h * 300 + k] : 0.f);
}

__global__ __launch_bounds__(256) void convert_ctx(const float* __restrict__ src)
{
    const long long idx = (long long)blockIdx.x * 256 + threadIdx.x;
    if (idx >= (long long)VOCAB * (CTXP / 8)) return;
    const int r  = (int)(idx / (CTXP / 8));
    const int c0 = (int)(idx - (long long)r * (CTXP / 8)) * 8;

    const float* sp = src + (size_t)r * EMBED + c0;
    float4 v0 = make_float4(0.f, 0.f, 0.f, 0.f);
    float4 v1 = make_float4(0.f, 0.f, 0.f, 0.f);
    if (c0 < 296) {
        v0 = *(const float4*)sp;
        v1 = *(const float4*)(sp + 4);
    } else if (c0 == 296) {
        v0 = *(const float4*)sp;
    }
    uint4 o;
    o.x = bf2_bits(v0.x, v0.y);
    o.y = bf2_bits(v0.z, v0.w);
    o.z = bf2_bits(v1.x, v1.y);
    o.w = bf2_bits(v1.z, v1.w);
    *(uint4*)(g_ctx + (size_t)r * CTXP + c0) = o;
}

// ---------------------------------------------------------------------------
// Kernel A: gather + GEMM1 (+logits/NLL) + GEMM2 (cv -> global bf16)
// Register-prefetched B stream: LDG of next chunk overlaps MMA of current.
// ---------------------------------------------------------------------------
__global__ __launch_bounds__(THREADS, 2) void gemm_kernel(
    const int* __restrict__ cen_ids,  const int* __restrict__ labels,
    const float* __restrict__ cen_emb,
    const float* __restrict__ b_enc,  const float* __restrict__ b_dec,
    const float* __restrict__ W_cls,  const float* __restrict__ b_cls)
{
    extern __shared__ char smc[];
    float* smf = (float*)smc;
    const uint32_t sb = smem_u32(smc);
    const int tid  = threadIdx.x;
    const int wid  = tid >> 5;
    const int lane = tid & 31;
    const int r0   = blockIdx.x * ROWS;

    // ---- constants + gather emb -> bf16 A tile ----
    for (int i = tid; i < 640; i += THREADS) {
        const int cls = i / KPAD, col = i - cls * KPAD;
        smf[SMF_WCLS + i] = (col < 300) ? W_cls[cls * 300 + col] : 0.f;
    }
    for (int i = tid; i < KPAD; i += THREADS) {
        smf[SMF_BENC + i] = (i < 300) ? b_enc[i] : 0.f;
        smf[SMF_BDEC + i] = (i < 300) ? b_dec[i] : 0.f;
    }
    for (int idx = tid; idx < ROWS * (KPAD / 2); idx += THREADS) {
        const int r = idx / (KPAD / 2);
        const int c = (idx - r * (KPAD / 2)) * 2;
        float2 v = make_float2(0.f, 0.f);
        if (c < 300)
            v = *(const float2*)(cen_emb + (size_t)cen_ids[r0 + r] * EMBED + c);
        *(uint32_t*)(smc + SMB_A + r * ROWB + c * 2) = bf2_bits(v.x, v.y);
    }

    const int mg    = wid & 3;
    const int nhalf = wid >> 2;
    const int m0    = mg * 16;
    const int rowA  = m0 + (lane >> 2);
    const int cq    = (lane & 3) * 2;
    float lg00 = 0.f, lg01 = 0.f, lg10 = 0.f, lg11 = 0.f;

    const uint32_t aAddrG0 = sb + SMB_A  + (uint32_t)(m0 + (lane & 15)) * ROWB
                           + (uint32_t)((lane >> 4) * 8) * 2;
    const uint32_t aAddrG1 = sb + SMB_A2 + (uint32_t)(m0 + (lane & 15)) * ROWB
                           + (uint32_t)((lane >> 4) * 8) * 2;
    const uint32_t bAddr0  = sb + SMB_B
                           + (uint32_t)(nhalf * 16 + ((lane >> 4) << 3) + (lane & 7)) * ROWB
                           + (uint32_t)(((lane >> 3) & 1) * 8) * 2;

    // prologue: prefetch step 0 (W_enc chunk 0). 32 rows x 40 uint4 = 5/thread.
    uint4 pre[5];
    {
        const uint4* src = (const uint4*)g_Wenc;
        #pragma unroll
        for (int k = 0; k < 5; ++k) pre[k] = src[tid + k * 256];
    }

    // ---- 20 linearized chunk-steps: g = step/10, chunk = step%10 ----
    #pragma unroll 1
    for (int step = 0; step < NSTEP; ++step) {
        const int g  = step / 10;
        const int n0 = (step - g * 10) * BCHUNK;

        __syncthreads();     // prior chunk's B reads (and A2 writes) done
        #pragma unroll
        for (int k = 0; k < 5; ++k) {
            const int i = tid + k * 256;
            const int r = i / 40, q = i - r * 40;
            *(uint4*)(smc + SMB_B + r * ROWB + q * 16) = pre[k];
        }
        __syncthreads();     // B chunk visible

        if (step + 1 < NSTEP) {      // prefetch next chunk (overlaps MMA below)
            const int s2 = step + 1, g2 = s2 / 10, c2 = s2 - g2 * 10;
            const uint4* src = (const uint4*)(g2 ? g_Wdec : g_Wenc) + c2 * (BCHUNK * 40);
            #pragma unroll
            for (int k = 0; k < 5; ++k) pre[k] = src[tid + k * 256];
        }

        float acc[2][4];
        #pragma unroll
        for (int j = 0; j < 2; ++j)
            #pragma unroll
            for (int i = 0; i < 4; ++i) acc[j][i] = 0.f;

        const uint32_t aAddr0 = g ? aAddrG1 : aAddrG0;
        #pragma unroll 5
        for (int ks = 0; ks < 20; ++ks) {
            uint32_t a[4], b[4];
            ldsm_x4(a, aAddr0 + ks * 32);
            ldsm_x4(b, bAddr0 + ks * 32);
            mma_bf16(acc[0], a, b);
            mma_bf16(acc[1], a, b + 2);
        }

        if (g == 0) {
            #pragma unroll
            for (int j = 0; j < 2; ++j) {
                const int c0 = n0 + nhalf * 16 + j * 8 + cq;
                const float be0 = smf[SMF_BENC + c0], be1 = smf[SMF_BENC + c0 + 1];
                const float v0 = acc[j][0] + be0, v1 = acc[j][1] + be1;
                const float v2 = acc[j][2] + be0, v3 = acc[j][3] + be1;
                const float w00 = smf[SMF_WCLS + c0],       w01 = smf[SMF_WCLS + c0 + 1];
                const float w10 = smf[SMF_WCLS + 320 + c0], w11 = smf[SMF_WCLS + 320 + c0 + 1];
                lg00 += v0 * w00 + v1 * w01;  lg01 += v0 * w10 + v1 * w11;
                lg10 += v2 * w00 + v3 * w01;  lg11 += v2 * w10 + v3 * w11;
                *(uint32_t*)(smc + SMB_A2 + rowA * ROWB + c0 * 2)       = bf2_bits(v0, v1);
                *(uint32_t*)(smc + SMB_A2 + (rowA + 8) * ROWB + c0 * 2) = bf2_bits(v2, v3);
            }
        } else {
            #pragma unroll
            for (int j = 0; j < 2; ++j) {
                const int c0 = n0 + nhalf * 16 + j * 8 + cq;
                if (c0 < CTXP) {
                    const float bd0 = smf[SMF_BDEC + c0], bd1 = smf[SMF_BDEC + c0 + 1];
                    *(uint32_t*)(g_cv + (size_t)(r0 + rowA) * CTXP + c0) =
                        bf2_bits(acc[j][0] + bd0, acc[j][1] + bd1);
                    *(uint32_t*)(g_cv + (size_t)(r0 + rowA + 8) * CTXP + c0) =
                        bf2_bits(acc[j][2] + bd0, acc[j][3] + bd1);
                }
            }
        }
    }

    // ---- logits -> NLL ----
    lg00 += __shfl_xor_sync(0xffffffffu, lg00, 1);
    lg00 += __shfl_xor_sync(0xffffffffu, lg00, 2);
    lg01 += __shfl_xor_sync(0xffffffffu, lg01, 1);
    lg01 += __shfl_xor_sync(0xffffffffu, lg01, 2);
    lg10 += __shfl_xor_sync(0xffffffffu, lg10, 1);
    lg10 += __shfl_xor_sync(0xffffffffu, lg10, 2);
    lg11 += __shfl_xor_sync(0xffffffffu, lg11, 1);
    lg11 += __shfl_xor_sync(0xffffffffu, lg11, 2);
    if ((lane & 3) == 0) {
        const int base = nhalf ? SMF_LGQ : SMF_LGP;
        smf[base + rowA * 2]           = lg00;
        smf[base + rowA * 2 + 1]       = lg01;
        smf[base + (rowA + 8) * 2]     = lg10;
        smf[base + (rowA + 8) * 2 + 1] = lg11;
    }
    __syncthreads();
    if (tid < ROWS) {
        const float l0 = smf[SMF_LGP + tid * 2]     + smf[SMF_LGQ + tid * 2]     + b_cls[0];
        const float l1 = smf[SMF_LGP + tid * 2 + 1] + smf[SMF_LGQ + tid * 2 + 1] + b_cls[1];
        const float m  = fmaxf(l0, l1);
        const float lse = m + log1pf(__expf(fminf(l0, l1) - m));
        smf[SMF_NLL + tid] = lse - (labels[r0 + tid] ? l1 : l0);
    }
    __syncthreads();
    if (tid == 0) {
        float sn = 0.f;
        #pragma unroll
        for (int i = 0; i < ROWS; ++i) sn += smf[SMF_NLL + i];
        g_nll[blockIdx.x] = sn;
    }
}

// ---------------------------------------------------------------------------
// Dot kernel: high-occupancy pos/neg score + deno loss. 64 rows/block.
// ---------------------------------------------------------------------------
__device__ __forceinline__ float dot8(uint4 c, uint4 x)
{
    const float2 c0 = __bfloat1622float2(*(const __nv_bfloat162*)&c.x);
    const float2 c1 = __bfloat1622float2(*(const __nv_bfloat162*)&c.y);
    const float2 c2 = __bfloat1622float2(*(const __nv_bfloat162*)&c.z);
    const float2 c3 = __bfloat1622float2(*(const __nv_bfloat162*)&c.w);
    const float2 x0 = __bfloat1622float2(*(const __nv_bfloat162*)&x.x);
    const float2 x1 = __bfloat1622float2(*(const __nv_bfloat162*)&x.y);
    const float2 x2 = __bfloat1622float2(*(const __nv_bfloat162*)&x.z);
    const float2 x3 = __bfloat1622float2(*(const __nv_bfloat162*)&x.w);
    return c0.x * x0.x + c0.y * x0.y + c1.x * x1.x + c1.y * x1.y
         + c2.x * x2.x + c2.y * x2.y + c3.x * x3.x + c3.y * x3.y;
}

__global__ __launch_bounds__(256) void dot_kernel(const int* __restrict__ ctx_ids,
                                                  const int* __restrict__ neg_ids)
{
    __shared__ float sden[32];
    const int tid  = threadIdx.x;
    const int wid  = tid >> 5;
    const int lane = tid & 31;
    const int o    = lane >> 3;
    const int l    = lane & 7;
    const int r0   = blockIdx.x * 64;

    float accDeno = 0.f;

    #pragma unroll 1
    for (int t = 0; t < 8; ++t) {
        const int gr = r0 + wid * 8 + t;
        const uint4* cv = (const uint4*)(g_cv + (size_t)gr * CTXP);

        #pragma unroll
        for (int round = 0; round < 3; ++round) {
            const int j = round * 4 + o;
            const bool valid = (j < 11);
            int widx = 0;
            if (valid) widx = (j == 0) ? ctx_ids[gr] : neg_ids[gr * KNEG + (j - 1)];
            const uint4* xp = (const uint4*)(g_ctx + (size_t)widx * CTXP);

            float acc = 0.f;
            #pragma unroll
            for (int s = 0; s < 5; ++s) {
                const int e = s * 8 + l;
                if (e < 38) acc += dot8(cv[e], xp[e]);
            }
            acc += __shfl_down_sync(0xffffffffu, acc, 4, 8);
            acc += __shfl_down_sync(0xffffffffu, acc, 2, 8);
            acc += __shfl_down_sync(0xffffffffu, acc, 1, 8);

            if (l == 0 && valid) {
                const float s1 = fminf(fmaxf(acc, -10.f), 10.f);
                accDeno += (j == 0) ? log1pf(__expf(-s1)) : log1pf(__expf(s1));
            }
        }
    }
    if (l == 0) sden[wid * 4 + o] = accDeno;
    __syncthreads();
    if (tid == 0) {
        float sd = 0.f;
        #pragma unroll
        for (int i = 0; i < 32; ++i) sd += sden[i];
        g_deno[blockIdx.x] = sd;
    }
}

__global__ __launch_bounds__(256) void finalize_kernel(float* __restrict__ out)
{
    __shared__ float sd[256], sn[256];
    const int t = threadIdx.x;
    sd[t] = g_deno[t] + g_deno[t + 256];
    sn[t] = g_nll[t]  + g_nll[t + 256];
    __syncthreads();
    for (int ofs = 128; ofs > 0; ofs >>= 1) {
        if (t < ofs) { sd[t] += sd[t + ofs]; sn[t] += sn[t + ofs]; }
        __syncthreads();
    }
    if (t == 0) {
        const float invB = 1.0f / (float)BATCH;
        float deno = fminf(fmaxf(sd[0] * invB, 1e-5f), 10.f);
        float cono = fminf(fmaxf(sn[0] * invB, 1e-5f), 10.f);
        out[0] = fmaxf(deno + cono, 1e-5f);
        out[1] = deno;
        out[2] = cono;
    }
}

extern "C" void kernel_launch(void* const* d_in, const int* in_sizes, int n_in,
                              void* d_out, int out_size)
{
    const int*   cen_ids = (const int*)  d_in[0];
    const int*   ctx_ids = (const int*)  d_in[1];
    const int*   neg_ids = (const int*)  d_in[2];
    const int*   labels  = (const int*)  d_in[3];
    const float* cen_emb = (const float*)d_in[4];
    const float* ctx_emb = (const float*)d_in[5];
    const float* W_enc   = (const float*)d_in[6];
    const float* b_enc   = (const float*)d_in[7];
    const float* W_dec   = (const float*)d_in[8];
    const float* b_dec   = (const float*)d_in[9];
    const float* W_cls   = (const float*)d_in[10];
    const float* b_cls   = (const float*)d_in[11];

    __nv_bfloat16* we;  cudaGetSymbolAddress((void**)&we, g_Wenc);
    __nv_bfloat16* wd;  cudaGetSymbolAddress((void**)&wd, g_Wdec);

    const int cBlocks = (KPAD * KPAD + 255) / 256;
    convert_w<<<cBlocks, 256>>>(we, W_enc);
    convert_w<<<cBlocks, 256>>>(wd, W_dec);

    const long long ctxThreads = (long long)VOCAB * (CTXP / 8);
    convert_ctx<<<(int)((ctxThreads + 255) / 256), 256>>>(ctx_emb);

    cudaFuncSetAttribute(gemm_kernel,
                         cudaFuncAttributeMaxDynamicSharedMemorySize, SM_TOTAL);
    gemm_kernel<<<NBLK, THREADS, SM_TOTAL>>>(
        cen_ids, labels, cen_emb, b_enc, b_dec, W_cls, b_cls);
    dot_kernel<<<NBLK, 256>>>(ctx_ids, neg_ids);
    finalize_kernel<<<1, 256>>>((float*)d_out);
}

// round 11
// speedup vs baseline: 1.1220x; 1.0268x over previous
#include <cuda_runtime.h>
#include <cuda_bf16.h>
#include <math.h>
#include <stdint.h>

#define BATCH   32768
#define ROWS    64
#define NBLK    (BATCH / ROWS)      // 512
#define EMBED   300
#define VOCAB   100000
#define CTXP    304                 // padded bf16 row (608 B)
#define KNEG    10
#define KPAD    320
#define THREADS 256
#define ROWB    656                 // smem row pitch bytes (328 bf16)
#define BCHUNK  32
#define NSTEP   20                  // 2 GEMMs x 10 chunks
#define CVT_PB  196                 // ctx rows converted per gemm block (512*196 >= 100000)

// ---- smem float-index layout ----
#define SMF_NLL   0
#define SMF_WCLS  96
#define SMF_BENC  736
#define SMF_BDEC  1056
#define SMF_LGP   1376
#define SMF_LGQ   1504
// ---- smem byte layout ----
#define SMB_A     6656
#define SMB_A2    (SMB_A  + ROWS * ROWB)      // 48640
#define SMB_B     (SMB_A2 + ROWS * ROWB)      // 90624
#define SM_TOTAL  (SMB_B  + BCHUNK * ROWB)    // 111616 -> 2 blocks/SM

__device__ __nv_bfloat16 g_Wenc[KPAD * KPAD];
__device__ __nv_bfloat16 g_Wdec[KPAD * KPAD];
__device__ __nv_bfloat16 g_ctx[(size_t)VOCAB * CTXP];
__device__ __nv_bfloat16 g_cv[(size_t)BATCH * CTXP];
__device__ float g_nll[NBLK];
__device__ float g_deno[1024];

__device__ __forceinline__ uint32_t smem_u32(const void* p) {
    uint32_t a;
    asm("{ .reg .u64 t; cvta.to.shared.u64 t, %1; cvt.u32.u64 %0, t; }" : "=r"(a) : "l"(p));
    return a;
}

__device__ __forceinline__ void ldsm_x4(uint32_t* r, uint32_t addr) {
    asm volatile("ldmatrix.sync.aligned.m8n8.x4.shared.b16 {%0,%1,%2,%3}, [%4];"
                 : "=r"(r[0]), "=r"(r[1]), "=r"(r[2]), "=r"(r[3]) : "r"(addr));
}

__device__ __forceinline__ void mma_bf16(float* d, const uint32_t* a, const uint32_t* b) {
    asm volatile("mma.sync.aligned.m16n8k16.row.col.f32.bf16.bf16.f32 "
                 "{%0,%1,%2,%3},{%4,%5,%6,%7},{%8,%9},{%0,%1,%2,%3};"
                 : "+f"(d[0]), "+f"(d[1]), "+f"(d[2]), "+f"(d[3])
                 : "r"(a[0]), "r"(a[1]), "r"(a[2]), "r"(a[3]), "r"(b[0]), "r"(b[1]));
}

__device__ __forceinline__ uint32_t bf2_bits(float lo, float hi) {
    __nv_bfloat162 t = __floats2bfloat162_rn(lo, hi);
    return *(uint32_t*)&t;
}

// ---------------------------------------------------------------------------
// Weight convert: fp32 [300][300] -> bf16 [320][320] zero-padded
// ---------------------------------------------------------------------------
__global__ __launch_bounds__(256) void convert_w(__nv_bfloat16* __restrict__ dst,
                                                 const float* __restrict__ src)
{
    const int idx = blockIdx.x * 256 + threadIdx.x;
    if (idx >= KPAD * KPAD) return;
    const int h = idx / KPAD;
    const int k = idx - h * KPAD;
    dst[idx] = __float2bfloat16((h < 300 && k < 300) ? src[h * 300 + k] : 0.f);
}

// ---------------------------------------------------------------------------
// Kernel A: ctx-slice convert + gather + GEMM1(+logits) + GEMM2 (cv -> global)
// ---------------------------------------------------------------------------
__global__ __launch_bounds__(THREADS, 2) void gemm_kernel(
    const int* __restrict__ cen_ids,  const int* __restrict__ labels,
    const float* __restrict__ cen_emb, const float* __restrict__ ctx_emb,
    const float* __restrict__ b_enc,  const float* __restrict__ b_dec,
    const float* __restrict__ W_cls,  const float* __restrict__ b_cls)
{
    extern __shared__ char smc[];
    float* smf = (float*)smc;
    const uint32_t sb = smem_u32(smc);
    const int tid  = threadIdx.x;
    const int wid  = tid >> 5;
    const int lane = tid & 31;
    const int r0   = blockIdx.x * ROWS;

    // ---- folded ctx convert: this block's 196-row slice of the bf16 table ----
    {
        const int base = blockIdx.x * CVT_PB;
        for (int i = tid; i < CVT_PB * (CTXP / 8); i += THREADS) {
            const int rr = i / (CTXP / 8);
            const int c0 = (i - rr * (CTXP / 8)) * 8;
            const int r  = base + rr;
            if (r < VOCAB) {
                const float* sp = ctx_emb + (size_t)r * EMBED + c0;
                float4 v0 = make_float4(0.f, 0.f, 0.f, 0.f);
                float4 v1 = make_float4(0.f, 0.f, 0.f, 0.f);
                if (c0 < 296) { v0 = *(const float4*)sp; v1 = *(const float4*)(sp + 4); }
                else if (c0 == 296) { v0 = *(const float4*)sp; }
                uint4 o;
                o.x = bf2_bits(v0.x, v0.y);
                o.y = bf2_bits(v0.z, v0.w);
                o.z = bf2_bits(v1.x, v1.y);
                o.w = bf2_bits(v1.z, v1.w);
                *(uint4*)(g_ctx + (size_t)r * CTXP + c0) = o;
            }
        }
    }

    // ---- constants + gather emb -> bf16 A tile ----
    for (int i = tid; i < 640; i += THREADS) {
        const int cls = i / KPAD, col = i - cls * KPAD;
        smf[SMF_WCLS + i] = (col < 300) ? W_cls[cls * 300 + col] : 0.f;
    }
    for (int i = tid; i < KPAD; i += THREADS) {
        smf[SMF_BENC + i] = (i < 300) ? b_enc[i] : 0.f;
        smf[SMF_BDEC + i] = (i < 300) ? b_dec[i] : 0.f;
    }
    for (int idx = tid; idx < ROWS * (KPAD / 2); idx += THREADS) {
        const int r = idx / (KPAD / 2);
        const int c = (idx - r * (KPAD / 2)) * 2;
        float2 v = make_float2(0.f, 0.f);
        if (c < 300)
            v = *(const float2*)(cen_emb + (size_t)cen_ids[r0 + r] * EMBED + c);
        *(uint32_t*)(smc + SMB_A + r * ROWB + c * 2) = bf2_bits(v.x, v.y);
    }

    const int mg    = wid & 3;
    const int nhalf = wid >> 2;
    const int m0    = mg * 16;
    const int rowA  = m0 + (lane >> 2);
    const int cq    = (lane & 3) * 2;
    float lg00 = 0.f, lg01 = 0.f, lg10 = 0.f, lg11 = 0.f;

    const uint32_t aAddrG0 = sb + SMB_A  + (uint32_t)(m0 + (lane & 15)) * ROWB
                           + (uint32_t)((lane >> 4) * 8) * 2;
    const uint32_t aAddrG1 = sb + SMB_A2 + (uint32_t)(m0 + (lane & 15)) * ROWB
                           + (uint32_t)((lane >> 4) * 8) * 2;
    const uint32_t bAddr0  = sb + SMB_B
                           + (uint32_t)(nhalf * 16 + ((lane >> 4) << 3) + (lane & 7)) * ROWB
                           + (uint32_t)(((lane >> 3) & 1) * 8) * 2;

    // prologue: prefetch step 0 (W_enc chunk 0)
    uint4 pre[5];
    {
        const uint4* src = (const uint4*)g_Wenc;
        #pragma unroll
        for (int k = 0; k < 5; ++k) pre[k] = src[tid + k * 256];
    }

    #pragma unroll 1
    for (int step = 0; step < NSTEP; ++step) {
        const int g  = step / 10;
        const int n0 = (step - g * 10) * BCHUNK;

        __syncthreads();
        #pragma unroll
        for (int k = 0; k < 5; ++k) {
            const int i = tid + k * 256;
            const int r = i / 40, q = i - r * 40;
            *(uint4*)(smc + SMB_B + r * ROWB + q * 16) = pre[k];
        }
        __syncthreads();

        if (step + 1 < NSTEP) {
            const int s2 = step + 1, g2 = s2 / 10, c2 = s2 - g2 * 10;
            const uint4* src = (const uint4*)(g2 ? g_Wdec : g_Wenc) + c2 * (BCHUNK * 40);
            #pragma unroll
            for (int k = 0; k < 5; ++k) pre[k] = src[tid + k * 256];
        }

        float acc[2][4];
        #pragma unroll
        for (int j = 0; j < 2; ++j)
            #pragma unroll
            for (int i = 0; i < 4; ++i) acc[j][i] = 0.f;

        const uint32_t aAddr0 = g ? aAddrG1 : aAddrG0;
        #pragma unroll 5
        for (int ks = 0; ks < 20; ++ks) {
            uint32_t a[4], b[4];
            ldsm_x4(a, aAddr0 + ks * 32);
            ldsm_x4(b, bAddr0 + ks * 32);
            mma_bf16(acc[0], a, b);
            mma_bf16(acc[1], a, b + 2);
        }

        if (g == 0) {
            #pragma unroll
            for (int j = 0; j < 2; ++j) {
                const int c0 = n0 + nhalf * 16 + j * 8 + cq;
                const float be0 = smf[SMF_BENC + c0], be1 = smf[SMF_BENC + c0 + 1];
                const float v0 = acc[j][0] + be0, v1 = acc[j][1] + be1;
                const float v2 = acc[j][2] + be0, v3 = acc[j][3] + be1;
                const float w00 = smf[SMF_WCLS + c0],       w01 = smf[SMF_WCLS + c0 + 1];
                const float w10 = smf[SMF_WCLS + 320 + c0], w11 = smf[SMF_WCLS + 320 + c0 + 1];
                lg00 += v0 * w00 + v1 * w01;  lg01 += v0 * w10 + v1 * w11;
                lg10 += v2 * w00 + v3 * w01;  lg11 += v2 * w10 + v3 * w11;
                *(uint32_t*)(smc + SMB_A2 + rowA * ROWB + c0 * 2)       = bf2_bits(v0, v1);
                *(uint32_t*)(smc + SMB_A2 + (rowA + 8) * ROWB + c0 * 2) = bf2_bits(v2, v3);
            }
        } else {
            #pragma unroll
            for (int j = 0; j < 2; ++j) {
                const int c0 = n0 + nhalf * 16 + j * 8 + cq;
                if (c0 < CTXP) {
                    const float bd0 = smf[SMF_BDEC + c0], bd1 = smf[SMF_BDEC + c0 + 1];
                    *(uint32_t*)(g_cv + (size_t)(r0 + rowA) * CTXP + c0) =
                        bf2_bits(acc[j][0] + bd0, acc[j][1] + bd1);
                    *(uint32_t*)(g_cv + (size_t)(r0 + rowA + 8) * CTXP + c0) =
                        bf2_bits(acc[j][2] + bd0, acc[j][3] + bd1);
                }
            }
        }
    }

    // ---- logits -> NLL ----
    lg00 += __shfl_xor_sync(0xffffffffu, lg00, 1);
    lg00 += __shfl_xor_sync(0xffffffffu, lg00, 2);
    lg01 += __shfl_xor_sync(0xffffffffu, lg01, 1);
    lg01 += __shfl_xor_sync(0xffffffffu, lg01, 2);
    lg10 += __shfl_xor_sync(0xffffffffu, lg10, 1);
    lg10 += __shfl_xor_sync(0xffffffffu, lg10, 2);
    lg11 += __shfl_xor_sync(0xffffffffu, lg11, 1);
    lg11 += __shfl_xor_sync(0xffffffffu, lg11, 2);
    if ((lane & 3) == 0) {
        const int base = nhalf ? SMF_LGQ : SMF_LGP;
        smf[base + rowA * 2]           = lg00;
        smf[base + rowA * 2 + 1]       = lg01;
        smf[base + (rowA + 8) * 2]     = lg10;
        smf[base + (rowA + 8) * 2 + 1] = lg11;
    }
    __syncthreads();
    if (tid < ROWS) {
        const float l0 = smf[SMF_LGP + tid * 2]     + smf[SMF_LGQ + tid * 2]     + b_cls[0];
        const float l1 = smf[SMF_LGP + tid * 2 + 1] + smf[SMF_LGQ + tid * 2 + 1] + b_cls[1];
        const float m  = fmaxf(l0, l1);
        const float lse = m + log1pf(__expf(fminf(l0, l1) - m));
        smf[SMF_NLL + tid] = lse - (labels[r0 + tid] ? l1 : l0);
    }
    __syncthreads();
    if (tid == 0) {
        float sn = 0.f;
        #pragma unroll
        for (int i = 0; i < ROWS; ++i) sn += smf[SMF_NLL + i];
        g_nll[blockIdx.x] = sn;
    }
}

// ---------------------------------------------------------------------------
// Dot kernel: 1024 blocks x 128 threads, 32 rows/block. cv loaded once per row.
// ---------------------------------------------------------------------------
__device__ __forceinline__ float dot8(uint4 c, uint4 x)
{
    const float2 c0 = __bfloat1622float2(*(const __nv_bfloat162*)&c.x);
    const float2 c1 = __bfloat1622float2(*(const __nv_bfloat162*)&c.y);
    const float2 c2 = __bfloat1622float2(*(const __nv_bfloat162*)&c.z);
    const float2 c3 = __bfloat1622float2(*(const __nv_bfloat162*)&c.w);
    const float2 x0 = __bfloat1622float2(*(const __nv_bfloat162*)&x.x);
    const float2 x1 = __bfloat1622float2(*(const __nv_bfloat162*)&x.y);
    const float2 x2 = __bfloat1622float2(*(const __nv_bfloat162*)&x.z);
    const float2 x3 = __bfloat1622float2(*(const __nv_bfloat162*)&x.w);
    return c0.x * x0.x + c0.y * x0.y + c1.x * x1.x + c1.y * x1.y
         + c2.x * x2.x + c2.y * x2.y + c3.x * x3.x + c3.y * x3.y;
}

__global__ __launch_bounds__(128) void dot_kernel(const int* __restrict__ ctx_ids,
                                                  const int* __restrict__ neg_ids)
{
    __shared__ float sden[16];
    const int tid  = threadIdx.x;
    const int wid  = tid >> 5;          // 0..3
    const int lane = tid & 31;
    const int o    = lane >> 3;
    const int l    = lane & 7;
    const int r0   = blockIdx.x * 32;

    float accDeno = 0.f;

    #pragma unroll 1
    for (int t = 0; t < 8; ++t) {
        const int gr = r0 + wid * 8 + t;
        const uint4* cv = (const uint4*)(g_cv + (size_t)gr * CTXP);

        // load this row's cv slice once (reused across all 3 rounds)
        uint4 cvr[5];
        #pragma unroll
        for (int s = 0; s < 5; ++s) {
            const int e = s * 8 + l;
            if (e < 38) cvr[s] = cv[e];
        }

        #pragma unroll
        for (int round = 0; round < 3; ++round) {
            const int j = round * 4 + o;
            const bool valid = (j < 11);
            int widx = 0;
            if (valid) widx = (j == 0) ? ctx_ids[gr] : neg_ids[gr * KNEG + (j - 1)];
            const uint4* xp = (const uint4*)(g_ctx + (size_t)widx * CTXP);

            float acc = 0.f;
            #pragma unroll
            for (int s = 0; s < 5; ++s) {
                const int e = s * 8 + l;
                if (e < 38) acc += dot8(cvr[s], xp[e]);
            }
            acc += __shfl_down_sync(0xffffffffu, acc, 4, 8);
            acc += __shfl_down_sync(0xffffffffu, acc, 2, 8);
            acc += __shfl_down_sync(0xffffffffu, acc, 1, 8);

            if (l == 0 && valid) {
                const float s1 = fminf(fmaxf(acc, -10.f), 10.f);
                accDeno += (j == 0) ? log1pf(__expf(-s1)) : log1pf(__expf(s1));
            }
        }
    }
    if (l == 0) sden[wid * 4 + o] = accDeno;
    __syncthreads();
    if (tid == 0) {
        float sd = 0.f;
        #pragma unroll
        for (int i = 0; i < 16; ++i) sd += sden[i];
        g_deno[blockIdx.x] = sd;
    }
}

__global__ __launch_bounds__(256) void finalize_kernel(float* __restrict__ out)
{
    __shared__ float sd[256], sn[256];
    const int t = threadIdx.x;
    sd[t] = g_deno[t] + g_deno[t + 256] + g_deno[t + 512] + g_deno[t + 768];
    sn[t] = g_nll[t]  + g_nll[t + 256];
    __syncthreads();
    for (int ofs = 128; ofs > 0; ofs >>= 1) {
        if (t < ofs) { sd[t] += sd[t + ofs]; sn[t] += sn[t + ofs]; }
        __syncthreads();
    }
    if (t == 0) {
        const float invB = 1.0f / (float)BATCH;
        float deno = fminf(fmaxf(sd[0] * invB, 1e-5f), 10.f);
        float cono = fminf(fmaxf(sn[0] * invB, 1e-5f), 10.f);
        out[0] = fmaxf(deno + cono, 1e-5f);
        out[1] = deno;
        out[2] = cono;
    }
}

extern "C" void kernel_launch(void* const* d_in, const int* in_sizes, int n_in,
                              void* d_out, int out_size)
{
    const int*   cen_ids = (const int*)  d_in[0];
    const int*   ctx_ids = (const int*)  d_in[1];
    const int*   neg_ids = (const int*)  d_in[2];
    const int*   labels  = (const int*)  d_in[3];
    const float* cen_emb = (const float*)d_in[4];
    const float* ctx_emb = (const float*)d_in[5];
    const float* W_enc   = (const float*)d_in[6];
    const float* b_enc   = (const float*)d_in[7];
    const float* W_dec   = (const float*)d_in[8];
    const float* b_dec   = (const float*)d_in[9];
    const float* W_cls   = (const float*)d_in[10];
    const float* b_cls   = (const float*)d_in[11];

    __nv_bfloat16* we;  cudaGetSymbolAddress((void**)&we, g_Wenc);
    __nv_bfloat16* wd;  cudaGetSymbolAddress((void**)&wd, g_Wdec);

    const int cBlocks = (KPAD * KPAD + 255) / 256;
    convert_w<<<cBlocks, 256>>>(we, W_enc);
    convert_w<<<cBlocks, 256>>>(wd, W_dec);

    cudaFuncSetAttribute(gemm_kernel,
                         cudaFuncAttributeMaxDynamicSharedMemorySize, SM_TOTAL);
    gemm_kernel<<<NBLK, THREADS, SM_TOTAL>>>(
        cen_ids, labels, cen_emb, ctx_emb, b_enc, b_dec, W_cls, b_cls);
    dot_kernel<<<1024, 128>>>(ctx_ids, neg_ids);
    finalize_kernel<<<1, 256>>>((float*)d_out);
}

// round 12
// speedup vs baseline: 1.2224x; 1.0895x over previous
#include <cuda_runtime.h>
#include <cuda_bf16.h>
#include <math.h>
#include <stdint.h>

#define BATCH   32768
#define ROWS    64
#define NBLK    (BATCH / ROWS)      // 512
#define EMBED   300
#define VOCAB   100000
#define CTXP    304                 // padded bf16 row (608 B)
#define KNEG    10
#define KPAD    320
#define THREADS 256
#define ROWB    656                 // smem row pitch bytes (328 bf16)
#define BCHUNK  32
#define NSTEP   20                  // 2 GEMMs x 10 chunks
#define CVT_PB  196                 // ctx rows per gemm block (512*196 >= 100000)
#define CVT_TASKS (CVT_PB * 38)     // uint4 convert tasks per block (7448)

// ---- smem float-index layout ----
#define SMF_NLL   0
#define SMF_WCLS  96
#define SMF_BENC  736
#define SMF_BDEC  1056
#define SMF_LGP   1376
#define SMF_LGQ   1504
// ---- smem byte layout ----
#define SMB_A     6656
#define SMB_A2    (SMB_A  + ROWS * ROWB)      // 48640
#define SMB_B     (SMB_A2 + ROWS * ROWB)      // 90624
#define SM_TOTAL  (SMB_B  + BCHUNK * ROWB)    // 111616 -> 2 blocks/SM

__device__ __nv_bfloat16 g_Wenc[KPAD * KPAD];
__device__ __nv_bfloat16 g_Wdec[KPAD * KPAD];
__device__ __nv_bfloat16 g_ctx[(size_t)VOCAB * CTXP];
__device__ __nv_bfloat16 g_cv[(size_t)BATCH * CTXP];
__device__ float g_nll[NBLK];
__device__ float g_deno[1024];

__device__ __forceinline__ uint32_t smem_u32(const void* p) {
    uint32_t a;
    asm("{ .reg .u64 t; cvta.to.shared.u64 t, %1; cvt.u32.u64 %0, t; }" : "=r"(a) : "l"(p));
    return a;
}

__device__ __forceinline__ void ldsm_x4(uint32_t* r, uint32_t addr) {
    asm volatile("ldmatrix.sync.aligned.m8n8.x4.shared.b16 {%0,%1,%2,%3}, [%4];"
                 : "=r"(r[0]), "=r"(r[1]), "=r"(r[2]), "=r"(r[3]) : "r"(addr));
}

__device__ __forceinline__ void mma_bf16(float* d, const uint32_t* a, const uint32_t* b) {
    asm volatile("mma.sync.aligned.m16n8k16.row.col.f32.bf16.bf16.f32 "
                 "{%0,%1,%2,%3},{%4,%5,%6,%7},{%8,%9},{%0,%1,%2,%3};"
                 : "+f"(d[0]), "+f"(d[1]), "+f"(d[2]), "+f"(d[3])
                 : "r"(a[0]), "r"(a[1]), "r"(a[2]), "r"(a[3]), "r"(b[0]), "r"(b[1]));
}

__device__ __forceinline__ uint32_t bf2_bits(float lo, float hi) {
    __nv_bfloat162 t = __floats2bfloat162_rn(lo, hi);
    return *(uint32_t*)&t;
}

#define BFMA2(acc, a, b) \
    asm("fma.rn.bf16x2 %0, %1, %2, %0;" : "+r"(acc) : "r"(a), "r"(b))

// ---------------------------------------------------------------------------
// Weight convert: fp32 [300][300] -> bf16 [320][320] zero-padded
// ---------------------------------------------------------------------------
__global__ __launch_bounds__(256) void convert_w(__nv_bfloat16* __restrict__ dst,
                                                 const float* __restrict__ src)
{
    const int idx = blockIdx.x * 256 + threadIdx.x;
    if (idx >= KPAD * KPAD) return;
    const int h = idx / KPAD;
    const int k = idx - h * KPAD;
    dst[idx] = __float2bfloat16((h < 300 && k < 300) ? src[h * 300 + k] : 0.f);
}

// ---------------------------------------------------------------------------
// Kernel A: gather + GEMM1(+logits) + GEMM2 (cv->global), with the ctx bf16
// convert spread across the 20 mainloop steps (overlaps MMA + barrier stalls).
// ---------------------------------------------------------------------------
__global__ __launch_bounds__(THREADS, 2) void gemm_kernel(
    const int* __restrict__ cen_ids,  const int* __restrict__ labels,
    const float* __restrict__ cen_emb, const float* __restrict__ ctx_emb,
    const float* __restrict__ b_enc,  const float* __restrict__ b_dec,
    const float* __restrict__ W_cls,  const float* __restrict__ b_cls)
{
    extern __shared__ char smc[];
    float* smf = (float*)smc;
    const uint32_t sb = smem_u32(smc);
    const int tid  = threadIdx.x;
    const int wid  = tid >> 5;
    const int lane = tid & 31;
    const int r0   = blockIdx.x * ROWS;
    const int cvtBase = blockIdx.x * CVT_PB;

    // ---- constants + gather emb -> bf16 A tile ----
    for (int i = tid; i < 640; i += THREADS) {
        const int cls = i / KPAD, col = i - cls * KPAD;
        smf[SMF_WCLS + i] = (col < 300) ? W_cls[cls * 300 + col] : 0.f;
    }
    for (int i = tid; i < KPAD; i += THREADS) {
        smf[SMF_BENC + i] = (i < 300) ? b_enc[i] : 0.f;
        smf[SMF_BDEC + i] = (i < 300) ? b_dec[i] : 0.f;
    }
    for (int idx = tid; idx < ROWS * (KPAD / 2); idx += THREADS) {
        const int r = idx / (KPAD / 2);
        const int c = (idx - r * (KPAD / 2)) * 2;
        float2 v = make_float2(0.f, 0.f);
        if (c < 300)
            v = *(const float2*)(cen_emb + (size_t)cen_ids[r0 + r] * EMBED + c);
        *(uint32_t*)(smc + SMB_A + r * ROWB + c * 2) = bf2_bits(v.x, v.y);
    }

    const int mg    = wid & 3;
    const int nhalf = wid >> 2;
    const int m0    = mg * 16;
    const int rowA  = m0 + (lane >> 2);
    const int cq    = (lane & 3) * 2;
    float lg00 = 0.f, lg01 = 0.f, lg10 = 0.f, lg11 = 0.f;

    const uint32_t aAddrG0 = sb + SMB_A  + (uint32_t)(m0 + (lane & 15)) * ROWB
                           + (uint32_t)((lane >> 4) * 8) * 2;
    const uint32_t aAddrG1 = sb + SMB_A2 + (uint32_t)(m0 + (lane & 15)) * ROWB
                           + (uint32_t)((lane >> 4) * 8) * 2;
    const uint32_t bAddr0  = sb + SMB_B
                           + (uint32_t)(nhalf * 16 + ((lane >> 4) << 3) + (lane & 7)) * ROWB
                           + (uint32_t)(((lane >> 3) & 1) * 8) * 2;

    // prologue: prefetch step 0 (W_enc chunk 0)
    uint4 pre[5];
    {
        const uint4* src = (const uint4*)g_Wenc;
        #pragma unroll
        for (int k = 0; k < 5; ++k) pre[k] = src[tid + k * 256];
    }

    #pragma unroll 1
    for (int step = 0; step < NSTEP; ++step) {
        const int g  = step / 10;
        const int n0 = (step - g * 10) * BCHUNK;

        __syncthreads();
        #pragma unroll
        for (int k = 0; k < 5; ++k) {
            const int i = tid + k * 256;
            const int r = i / 40, q = i - r * 40;
            *(uint4*)(smc + SMB_B + r * ROWB + q * 16) = pre[k];
        }
        __syncthreads();

        if (step + 1 < NSTEP) {
            const int s2 = step + 1, g2 = s2 / 10, c2 = s2 - g2 * 10;
            const uint4* src = (const uint4*)(g2 ? g_Wdec : g_Wenc) + c2 * (BCHUNK * 40);
            #pragma unroll
            for (int k = 0; k < 5; ++k) pre[k] = src[tid + k * 256];
        }

        // ---- interleaved ctx convert slice (overlaps MMA below) ----
        #pragma unroll
        for (int k = 0; k < 2; ++k) {
            const int task = step * (2 * THREADS) + k * THREADS + tid;
            if (task < CVT_TASKS) {
                const int rr = task / 38;
                const int c0 = (task - rr * 38) * 8;
                const int r  = cvtBase + rr;
                if (r < VOCAB) {
                    const float* sp = ctx_emb + (size_t)r * EMBED + c0;
                    float4 v0 = make_float4(0.f, 0.f, 0.f, 0.f);
                    float4 v1 = make_float4(0.f, 0.f, 0.f, 0.f);
                    if (c0 < 296) { v0 = *(const float4*)sp; v1 = *(const float4*)(sp + 4); }
                    else if (c0 == 296) { v0 = *(const float4*)sp; }
                    uint4 o;
                    o.x = bf2_bits(v0.x, v0.y);
                    o.y = bf2_bits(v0.z, v0.w);
                    o.z = bf2_bits(v1.x, v1.y);
                    o.w = bf2_bits(v1.z, v1.w);
                    *(uint4*)(g_ctx + (size_t)r * CTXP + c0) = o;
                }
            }
        }

        float acc[2][4];
        #pragma unroll
        for (int j = 0; j < 2; ++j)
            #pragma unroll
            for (int i = 0; i < 4; ++i) acc[j][i] = 0.f;

        const uint32_t aAddr0 = g ? aAddrG1 : aAddrG0;
        #pragma unroll 5
        for (int ks = 0; ks < 20; ++ks) {
            uint32_t a[4], b[4];
            ldsm_x4(a, aAddr0 + ks * 32);
            ldsm_x4(b, bAddr0 + ks * 32);
            mma_bf16(acc[0], a, b);
            mma_bf16(acc[1], a, b + 2);
        }

        if (g == 0) {
            #pragma unroll
            for (int j = 0; j < 2; ++j) {
                const int c0 = n0 + nhalf * 16 + j * 8 + cq;
                const float be0 = smf[SMF_BENC + c0], be1 = smf[SMF_BENC + c0 + 1];
                const float v0 = acc[j][0] + be0, v1 = acc[j][1] + be1;
                const float v2 = acc[j][2] + be0, v3 = acc[j][3] + be1;
                const float w00 = smf[SMF_WCLS + c0],       w01 = smf[SMF_WCLS + c0 + 1];
                const float w10 = smf[SMF_WCLS + 320 + c0], w11 = smf[SMF_WCLS + 320 + c0 + 1];
                lg00 += v0 * w00 + v1 * w01;  lg01 += v0 * w10 + v1 * w11;
                lg10 += v2 * w00 + v3 * w01;  lg11 += v2 * w10 + v3 * w11;
                *(uint32_t*)(smc + SMB_A2 + rowA * ROWB + c0 * 2)       = bf2_bits(v0, v1);
                *(uint32_t*)(smc + SMB_A2 + (rowA + 8) * ROWB + c0 * 2) = bf2_bits(v2, v3);
            }
        } else {
            #pragma unroll
            for (int j = 0; j < 2; ++j) {
                const int c0 = n0 + nhalf * 16 + j * 8 + cq;
                if (c0 < CTXP) {
                    const float bd0 = smf[SMF_BDEC + c0], bd1 = smf[SMF_BDEC + c0 + 1];
                    *(uint32_t*)(g_cv + (size_t)(r0 + rowA) * CTXP + c0) =
                        bf2_bits(acc[j][0] + bd0, acc[j][1] + bd1);
                    *(uint32_t*)(g_cv + (size_t)(r0 + rowA + 8) * CTXP + c0) =
                        bf2_bits(acc[j][2] + bd0, acc[j][3] + bd1);
                }
            }
        }
    }

    // ---- logits -> NLL ----
    lg00 += __shfl_xor_sync(0xffffffffu, lg00, 1);
    lg00 += __shfl_xor_sync(0xffffffffu, lg00, 2);
    lg01 += __shfl_xor_sync(0xffffffffu, lg01, 1);
    lg01 += __shfl_xor_sync(0xffffffffu, lg01, 2);
    lg10 += __shfl_xor_sync(0xffffffffu, lg10, 1);
    lg10 += __shfl_xor_sync(0xffffffffu, lg10, 2);
    lg11 += __shfl_xor_sync(0xffffffffu, lg11, 1);
    lg11 += __shfl_xor_sync(0xffffffffu, lg11, 2);
    if ((lane & 3) == 0) {
        const int base = nhalf ? SMF_LGQ : SMF_LGP;
        smf[base + rowA * 2]           = lg00;
        smf[base + rowA * 2 + 1]       = lg01;
        smf[base + (rowA + 8) * 2]     = lg10;
        smf[base + (rowA + 8) * 2 + 1] = lg11;
    }
    __syncthreads();
    if (tid < ROWS) {
        const float l0 = smf[SMF_LGP + tid * 2]     + smf[SMF_LGQ + tid * 2]     + b_cls[0];
        const float l1 = smf[SMF_LGP + tid * 2 + 1] + smf[SMF_LGQ + tid * 2 + 1] + b_cls[1];
        const float m  = fmaxf(l0, l1);
        const float lse = m + log1pf(__expf(fminf(l0, l1) - m));
        smf[SMF_NLL + tid] = lse - (labels[r0 + tid] ? l1 : l0);
    }
    __syncthreads();
    if (tid == 0) {
        float sn = 0.f;
        #pragma unroll
        for (int i = 0; i < ROWS; ++i) sn += smf[SMF_NLL + i];
        g_nll[blockIdx.x] = sn;
    }
}

// ---------------------------------------------------------------------------
// Dot kernel: bf16x2-FMA accumulation (4x fewer inner instructions).
// 1024 blocks x 128 threads, 32 rows/block.
// ---------------------------------------------------------------------------
__global__ __launch_bounds__(128) void dot_kernel(const int* __restrict__ ctx_ids,
                                                  const int* __restrict__ neg_ids)
{
    __shared__ float sden[16];
    const int tid  = threadIdx.x;
    const int wid  = tid >> 5;          // 0..3
    const int lane = tid & 31;
    const int o    = lane >> 3;
    const int l    = lane & 7;
    const int r0   = blockIdx.x * 32;

    float accDeno = 0.f;

    #pragma unroll 1
    for (int t = 0; t < 8; ++t) {
        const int gr = r0 + wid * 8 + t;
        const uint4* cv = (const uint4*)(g_cv + (size_t)gr * CTXP);

        uint4 cvr[5];
        #pragma unroll
        for (int s = 0; s < 5; ++s) {
            const int e = s * 8 + l;
            cvr[s] = (e < 38) ? cv[e] : make_uint4(0u, 0u, 0u, 0u);
        }

        #pragma unroll
        for (int round = 0; round < 3; ++round) {
            const int j = round * 4 + o;
            const bool valid = (j < 11);
            int widx = 0;
            if (valid) widx = (j == 0) ? ctx_ids[gr] : neg_ids[gr * KNEG + (j - 1)];
            const uint4* xp = (const uint4*)(g_ctx + (size_t)widx * CTXP);

            uint32_t a0 = 0u, a1 = 0u;      // packed bf16x2 accumulators
            #pragma unroll
            for (int s = 0; s < 5; ++s) {
                const int e = s * 8 + l;
                if (e < 38) {
                    const uint4 x = xp[e];
                    BFMA2(a0, cvr[s].x, x.x);
                    BFMA2(a1, cvr[s].y, x.y);
                    BFMA2(a0, cvr[s].z, x.z);
                    BFMA2(a1, cvr[s].w, x.w);
                }
            }
            const float2 f0 = __bfloat1622float2(*(const __nv_bfloat162*)&a0);
            const float2 f1 = __bfloat1622float2(*(const __nv_bfloat162*)&a1);
            float acc = (f0.x + f0.y) + (f1.x + f1.y);

            acc += __shfl_down_sync(0xffffffffu, acc, 4, 8);
            acc += __shfl_down_sync(0xffffffffu, acc, 2, 8);
            acc += __shfl_down_sync(0xffffffffu, acc, 1, 8);

            if (l == 0 && valid) {
                const float s1 = fminf(fmaxf(acc, -10.f), 10.f);
                accDeno += (j == 0) ? log1pf(__expf(-s1)) : log1pf(__expf(s1));
            }
        }
    }
    if (l == 0) sden[wid * 4 + o] = accDeno;
    __syncthreads();
    if (tid == 0) {
        float sd = 0.f;
        #pragma unroll
        for (int i = 0; i < 16; ++i) sd += sden[i];
        g_deno[blockIdx.x] = sd;
    }
}

__global__ __launch_bounds__(256) void finalize_kernel(float* __restrict__ out)
{
    __shared__ float sd[256], sn[256];
    const int t = threadIdx.x;
    sd[t] = g_deno[t] + g_deno[t + 256] + g_deno[t + 512] + g_deno[t + 768];
    sn[t] = g_nll[t]  + g_nll[t + 256];
    __syncthreads();
    for (int ofs = 128; ofs > 0; ofs >>= 1) {
        if (t < ofs) { sd[t] += sd[t + ofs]; sn[t] += sn[t + ofs]; }
        __syncthreads();
    }
    if (t == 0) {
        const float invB = 1.0f / (float)BATCH;
        float deno = fminf(fmaxf(sd[0] * invB, 1e-5f), 10.f);
        float cono = fminf(fmaxf(sn[0] * invB, 1e-5f), 10.f);
        out[0] = fmaxf(deno + cono, 1e-5f);
        out[1] = deno;
        out[2] = cono;
    }
}

extern "C" void kernel_launch(void* const* d_in, const int* in_sizes, int n_in,
                              void* d_out, int out_size)
{
    const int*   cen_ids = (const int*)  d_in[0];
    const int*   ctx_ids = (const int*)  d_in[1];
    const int*   neg_ids = (const int*)  d_in[2];
    const int*   labels  = (const int*)  d_in[3];
    const float* cen_emb = (const float*)d_in[4];
    const float* ctx_emb = (const float*)d_in[5];
    const float* W_enc   = (const float*)d_in[6];
    const float* b_enc   = (const float*)d_in[7];
    const float* W_dec   = (const float*)d_in[8];
    const float* b_dec   = (const float*)d_in[9];
    const float* W_cls   = (const float*)d_in[10];
    const float* b_cls   = (const float*)d_in[11];

    __nv_bfloat16* we;  cudaGetSymbolAddress((void**)&we, g_Wenc);
    __nv_bfloat16* wd;  cudaGetSymbolAddress((void**)&wd, g_Wdec);

    const int cBlocks = (KPAD * KPAD + 255) / 256;
    convert_w<<<cBlocks, 256>>>(we, W_enc);
    convert_w<<<cBlocks, 256>>>(wd, W_dec);

    cudaFuncSetAttribute(gemm_kernel,
                         cudaFuncAttributeMaxDynamicSharedMemorySize, SM_TOTAL);
    gemm_kernel<<<NBLK, THREADS, SM_TOTAL>>>(
        cen_ids, labels, cen_emb, ctx_emb, b_enc, b_dec, W_cls, b_cls);
    dot_kernel<<<1024, 128>>>(ctx_ids, neg_ids);
    finalize_kernel<<<1, 256>>>((float*)d_out);
}

// round 13
// speedup vs baseline: 1.2611x; 1.0316x over previous
#include <cuda_runtime.h>
#include <cuda_bf16.h>
#include <math.h>
#include <stdint.h>

#define BATCH   32768
#define ROWS    64
#define NBLK    (BATCH / ROWS)      // 512 gemm blocks
#define CVTBLK  128                 // ctx-convert blocks (prepended)
#define GRID    (NBLK + CVTBLK)     // 640
#define EMBED   300
#define VOCAB   100000
#define CTXP    304                 // padded bf16 row (608 B)
#define KNEG    10
#define KPAD    320
#define THREADS 256
#define ROWB    656                 // smem row pitch bytes (328 bf16)
#define BCHUNK  32
#define NSTEP   20                  // 2 GEMMs x 10 chunks

// ---- smem float-index layout ----
#define SMF_NLL   0
#define SMF_WCLS  96
#define SMF_BENC  736
#define SMF_BDEC  1056
#define SMF_LGP   1376
#define SMF_LGQ   1504
// ---- smem byte layout ----
#define SMB_A     6656
#define SMB_A2    (SMB_A  + ROWS * ROWB)      // 48640
#define SMB_B     (SMB_A2 + ROWS * ROWB)      // 90624
#define SM_TOTAL  (SMB_B  + BCHUNK * ROWB)    // 111616 -> 2 blocks/SM

__device__ __nv_bfloat16 g_Wenc[KPAD * KPAD];
__device__ __nv_bfloat16 g_Wdec[KPAD * KPAD];
__device__ __nv_bfloat16 g_ctx[(size_t)VOCAB * CTXP];
__device__ __nv_bfloat16 g_cv[(size_t)BATCH * CTXP];
__device__ float g_nll[NBLK];
__device__ float g_deno[1024];

__device__ __forceinline__ uint32_t smem_u32(const void* p) {
    uint32_t a;
    asm("{ .reg .u64 t; cvta.to.shared.u64 t, %1; cvt.u32.u64 %0, t; }" : "=r"(a) : "l"(p));
    return a;
}

__device__ __forceinline__ void ldsm_x4(uint32_t* r, uint32_t addr) {
    asm volatile("ldmatrix.sync.aligned.m8n8.x4.shared.b16 {%0,%1,%2,%3}, [%4];"
                 : "=r"(r[0]), "=r"(r[1]), "=r"(r[2]), "=r"(r[3]) : "r"(addr));
}

__device__ __forceinline__ void mma_bf16(float* d, const uint32_t* a, const uint32_t* b) {
    asm volatile("mma.sync.aligned.m16n8k16.row.col.f32.bf16.bf16.f32 "
                 "{%0,%1,%2,%3},{%4,%5,%6,%7},{%8,%9},{%0,%1,%2,%3};"
                 : "+f"(d[0]), "+f"(d[1]), "+f"(d[2]), "+f"(d[3])
                 : "r"(a[0]), "r"(a[1]), "r"(a[2]), "r"(a[3]), "r"(b[0]), "r"(b[1]));
}

__device__ __forceinline__ uint32_t bf2_bits(float lo, float hi) {
    __nv_bfloat162 t = __floats2bfloat162_rn(lo, hi);
    return *(uint32_t*)&t;
}

#define BFMA2(acc, a, b) \
    asm("fma.rn.bf16x2 %0, %1, %2, %0;" : "+r"(acc) : "r"(a), "r"(b))

// ---------------------------------------------------------------------------
// Weight convert: fp32 [300][300] -> bf16 [320][320] zero-padded
// (separate kernel: must complete before any gemm block's weight prefetch)
// ---------------------------------------------------------------------------
__global__ __launch_bounds__(256) void convert_w(__nv_bfloat16* __restrict__ dst,
                                                 const float* __restrict__ src)
{
    const int idx = blockIdx.x * 256 + threadIdx.x;
    if (idx >= KPAD * KPAD) return;
    const int h = idx / KPAD;
    const int k = idx - h * KPAD;
    dst[idx] = __float2bfloat16((h < 300 && k < 300) ? src[h * 300 + k] : 0.f);
}

// ---------------------------------------------------------------------------
// Heterogeneous kernel: blocks [0,128) stream-convert ctx_emb -> g_ctx;
// blocks [128,640) run the clean GEMM pipeline. Convert DRAM traffic overlaps
// gemm MMA at block granularity.
// ---------------------------------------------------------------------------
__global__ __launch_bounds__(THREADS, 2) void hetero_kernel(
    const int* __restrict__ cen_ids,  const int* __restrict__ labels,
    const float* __restrict__ cen_emb, const float* __restrict__ ctx_emb,
    const float* __restrict__ b_enc,  const float* __restrict__ b_dec,
    const float* __restrict__ W_cls,  const float* __restrict__ b_cls)
{
    const int tid = threadIdx.x;

    // ================= convert blocks =================
    if (blockIdx.x < CVTBLK) {
        const int total = VOCAB * 38;
        for (int i = blockIdx.x * THREADS + tid; i < total; i += CVTBLK * THREADS) {
            const int r  = i / 38;
            const int c0 = (i - r * 38) * 8;
            const float* sp = ctx_emb + (size_t)r * EMBED + c0;
            float4 v0 = make_float4(0.f, 0.f, 0.f, 0.f);
            float4 v1 = make_float4(0.f, 0.f, 0.f, 0.f);
            if (c0 < 296) { v0 = *(const float4*)sp; v1 = *(const float4*)(sp + 4); }
            else if (c0 == 296) { v0 = *(const float4*)sp; }
            uint4 o;
            o.x = bf2_bits(v0.x, v0.y);
            o.y = bf2_bits(v0.z, v0.w);
            o.z = bf2_bits(v1.x, v1.y);
            o.w = bf2_bits(v1.z, v1.w);
            *(uint4*)(g_ctx + (size_t)r * CTXP + c0) = o;
        }
        return;
    }

    // ================= gemm blocks =================
    extern __shared__ char smc[];
    float* smf = (float*)smc;
    const uint32_t sb = smem_u32(smc);
    const int gb   = blockIdx.x - CVTBLK;
    const int wid  = tid >> 5;
    const int lane = tid & 31;
    const int r0   = gb * ROWS;

    for (int i = tid; i < 640; i += THREADS) {
        const int cls = i / KPAD, col = i - cls * KPAD;
        smf[SMF_WCLS + i] = (col < 300) ? W_cls[cls * 300 + col] : 0.f;
    }
    for (int i = tid; i < KPAD; i += THREADS) {
        smf[SMF_BENC + i] = (i < 300) ? b_enc[i] : 0.f;
        smf[SMF_BDEC + i] = (i < 300) ? b_dec[i] : 0.f;
    }
    for (int idx = tid; idx < ROWS * (KPAD / 2); idx += THREADS) {
        const int r = idx / (KPAD / 2);
        const int c = (idx - r * (KPAD / 2)) * 2;
        float2 v = make_float2(0.f, 0.f);
        if (c < 300)
            v = *(const float2*)(cen_emb + (size_t)cen_ids[r0 + r] * EMBED + c);
        *(uint32_t*)(smc + SMB_A + r * ROWB + c * 2) = bf2_bits(v.x, v.y);
    }

    const int mg    = wid & 3;
    const int nhalf = wid >> 2;
    const int m0    = mg * 16;
    const int rowA  = m0 + (lane >> 2);
    const int cq    = (lane & 3) * 2;
    float lg00 = 0.f, lg01 = 0.f, lg10 = 0.f, lg11 = 0.f;

    const uint32_t aAddrG0 = sb + SMB_A  + (uint32_t)(m0 + (lane & 15)) * ROWB
                           + (uint32_t)((lane >> 4) * 8) * 2;
    const uint32_t aAddrG1 = sb + SMB_A2 + (uint32_t)(m0 + (lane & 15)) * ROWB
                           + (uint32_t)((lane >> 4) * 8) * 2;
    const uint32_t bAddr0  = sb + SMB_B
                           + (uint32_t)(nhalf * 16 + ((lane >> 4) << 3) + (lane & 7)) * ROWB
                           + (uint32_t)(((lane >> 3) & 1) * 8) * 2;

    uint4 pre[5];
    {
        const uint4* src = (const uint4*)g_Wenc;
        #pragma unroll
        for (int k = 0; k < 5; ++k) pre[k] = src[tid + k * 256];
    }

    #pragma unroll 1
    for (int step = 0; step < NSTEP; ++step) {
        const int g  = step / 10;
        const int n0 = (step - g * 10) * BCHUNK;

        __syncthreads();
        #pragma unroll
        for (int k = 0; k < 5; ++k) {
            const int i = tid + k * 256;
            const int r = i / 40, q = i - r * 40;
            *(uint4*)(smc + SMB_B + r * ROWB + q * 16) = pre[k];
        }
        __syncthreads();

        if (step + 1 < NSTEP) {
            const int s2 = step + 1, g2 = s2 / 10, c2 = s2 - g2 * 10;
            const uint4* src = (const uint4*)(g2 ? g_Wdec : g_Wenc) + c2 * (BCHUNK * 40);
            #pragma unroll
            for (int k = 0; k < 5; ++k) pre[k] = src[tid + k * 256];
        }

        float acc[2][4];
        #pragma unroll
        for (int j = 0; j < 2; ++j)
            #pragma unroll
            for (int i = 0; i < 4; ++i) acc[j][i] = 0.f;

        const uint32_t aAddr0 = g ? aAddrG1 : aAddrG0;
        #pragma unroll 5
        for (int ks = 0; ks < 20; ++ks) {
            uint32_t a[4], b[4];
            ldsm_x4(a, aAddr0 + ks * 32);
            ldsm_x4(b, bAddr0 + ks * 32);
            mma_bf16(acc[0], a, b);
            mma_bf16(acc[1], a, b + 2);
        }

        if (g == 0) {
            #pragma unroll
            for (int j = 0; j < 2; ++j) {
                const int c0 = n0 + nhalf * 16 + j * 8 + cq;
                const float be0 = smf[SMF_BENC + c0], be1 = smf[SMF_BENC + c0 + 1];
                const float v0 = acc[j][0] + be0, v1 = acc[j][1] + be1;
                const float v2 = acc[j][2] + be0, v3 = acc[j][3] + be1;
                const float w00 = smf[SMF_WCLS + c0],       w01 = smf[SMF_WCLS + c0 + 1];
                const float w10 = smf[SMF_WCLS + 320 + c0], w11 = smf[SMF_WCLS + 320 + c0 + 1];
                lg00 += v0 * w00 + v1 * w01;  lg01 += v0 * w10 + v1 * w11;
                lg10 += v2 * w00 + v3 * w01;  lg11 += v2 * w10 + v3 * w11;
                *(uint32_t*)(smc + SMB_A2 + rowA * ROWB + c0 * 2)       = bf2_bits(v0, v1);
                *(uint32_t*)(smc + SMB_A2 + (rowA + 8) * ROWB + c0 * 2) = bf2_bits(v2, v3);
            }
        } else {
            #pragma unroll
            for (int j = 0; j < 2; ++j) {
                const int c0 = n0 + nhalf * 16 + j * 8 + cq;
                if (c0 < CTXP) {
                    const float bd0 = smf[SMF_BDEC + c0], bd1 = smf[SMF_BDEC + c0 + 1];
                    *(uint32_t*)(g_cv + (size_t)(r0 + rowA) * CTXP + c0) =
                        bf2_bits(acc[j][0] + bd0, acc[j][1] + bd1);
                    *(uint32_t*)(g_cv + (size_t)(r0 + rowA + 8) * CTXP + c0) =
                        bf2_bits(acc[j][2] + bd0, acc[j][3] + bd1);
                }
            }
        }
    }

    // ---- logits -> NLL ----
    lg00 += __shfl_xor_sync(0xffffffffu, lg00, 1);
    lg00 += __shfl_xor_sync(0xffffffffu, lg00, 2);
    lg01 += __shfl_xor_sync(0xffffffffu, lg01, 1);
    lg01 += __shfl_xor_sync(0xffffffffu, lg01, 2);
    lg10 += __shfl_xor_sync(0xffffffffu, lg10, 1);
    lg10 += __shfl_xor_sync(0xffffffffu, lg10, 2);
    lg11 += __shfl_xor_sync(0xffffffffu, lg11, 1);
    lg11 += __shfl_xor_sync(0xffffffffu, lg11, 2);
    if ((lane & 3) == 0) {
        const int base = nhalf ? SMF_LGQ : SMF_LGP;
        smf[base + rowA * 2]           = lg00;
        smf[base + rowA * 2 + 1]       = lg01;
        smf[base + (rowA + 8) * 2]     = lg10;
        smf[base + (rowA + 8) * 2 + 1] = lg11;
    }
    __syncthreads();
    if (tid < ROWS) {
        const float l0 = smf[SMF_LGP + tid * 2]     + smf[SMF_LGQ + tid * 2]     + b_cls[0];
        const float l1 = smf[SMF_LGP + tid * 2 + 1] + smf[SMF_LGQ + tid * 2 + 1] + b_cls[1];
        const float m  = fmaxf(l0, l1);
        const float lse = m + log1pf(__expf(fminf(l0, l1) - m));
        smf[SMF_NLL + tid] = lse - (labels[r0 + tid] ? l1 : l0);
    }
    __syncthreads();
    if (tid == 0) {
        float sn = 0.f;
        #pragma unroll
        for (int i = 0; i < ROWS; ++i) sn += smf[SMF_NLL + i];
        g_nll[gb] = sn;
    }
}

// ---------------------------------------------------------------------------
// Dot kernel: bf16x2 FMA + software-pipelined gather rounds.
// ---------------------------------------------------------------------------
__device__ __forceinline__ void load5(uint4* x, const uint4* xp, int l)
{
    #pragma unroll
    for (int s = 0; s < 5; ++s) {
        const int e = s * 8 + l;
        x[s] = (e < 38) ? xp[e] : make_uint4(0u, 0u, 0u, 0u);
    }
}

__device__ __forceinline__ float dot_round(const uint4* cvr, const uint4* x)
{
    uint32_t a0 = 0u, a1 = 0u;
    #pragma unroll
    for (int s = 0; s < 5; ++s) {
        BFMA2(a0, cvr[s].x, x[s].x);
        BFMA2(a1, cvr[s].y, x[s].y);
        BFMA2(a0, cvr[s].z, x[s].z);
        BFMA2(a1, cvr[s].w, x[s].w);
    }
    const float2 f0 = __bfloat1622float2(*(const __nv_bfloat162*)&a0);
    const float2 f1 = __bfloat1622float2(*(const __nv_bfloat162*)&a1);
    return (f0.x + f0.y) + (f1.x + f1.y);
}

__global__ __launch_bounds__(128) void dot_kernel(const int* __restrict__ ctx_ids,
                                                  const int* __restrict__ neg_ids)
{
    __shared__ float sden[16];
    const int tid  = threadIdx.x;
    const int wid  = tid >> 5;
    const int lane = tid & 31;
    const int o    = lane >> 3;
    const int l    = lane & 7;
    const int r0   = blockIdx.x * 32;

    float accDeno = 0.f;

    #pragma unroll 1
    for (int t = 0; t < 8; ++t) {
        const int gr = r0 + wid * 8 + t;
        const uint4* cv = (const uint4*)(g_cv + (size_t)gr * CTXP);

        uint4 cvr[5];
        load5(cvr, cv, l);

        // round ids: r0 -> j=o (pos if o==0), r1 -> j=4+o, r2 -> j=8+o (o<3)
        const int id0 = (o == 0) ? ctx_ids[gr] : neg_ids[gr * KNEG + (o - 1)];
        const int id1 = neg_ids[gr * KNEG + 3 + o];
        const int id2 = (o < 3) ? neg_ids[gr * KNEG + 7 + o] : 0;

        uint4 xa[5], xb[5];
        load5(xa, (const uint4*)(g_ctx + (size_t)id0 * CTXP), l);
        load5(xb, (const uint4*)(g_ctx + (size_t)id1 * CTXP), l);

        // ---- round 0 (xa) ----
        {
            float acc = dot_round(cvr, xa);
            // refill xa with round 2 while round 0 reduces
            load5(xa, (const uint4*)(g_ctx + (size_t)id2 * CTXP), l);
            acc += __shfl_down_sync(0xffffffffu, acc, 4, 8);
            acc += __shfl_down_sync(0xffffffffu, acc, 2, 8);
            acc += __shfl_down_sync(0xffffffffu, acc, 1, 8);
            if (l == 0) {
                const float s1 = fminf(fmaxf(acc, -10.f), 10.f);
                accDeno += (o == 0) ? log1pf(__expf(-s1)) : log1pf(__expf(s1));
            }
        }
        // ---- round 1 (xb) ----
        {
            float acc = dot_round(cvr, xb);
            acc += __shfl_down_sync(0xffffffffu, acc, 4, 8);
            acc += __shfl_down_sync(0xffffffffu, acc, 2, 8);
            acc += __shfl_down_sync(0xffffffffu, acc, 1, 8);
            if (l == 0) {
                const float s1 = fminf(fmaxf(acc, -10.f), 10.f);
                accDeno += log1pf(__expf(s1));
            }
        }
        // ---- round 2 (xa refilled) ----
        {
            float acc = dot_round(cvr, xa);
            acc += __shfl_down_sync(0xffffffffu, acc, 4, 8);
            acc += __shfl_down_sync(0xffffffffu, acc, 2, 8);
            acc += __shfl_down_sync(0xffffffffu, acc, 1, 8);
            if (l == 0 && o < 3) {
                const float s1 = fminf(fmaxf(acc, -10.f), 10.f);
                accDeno += log1pf(__expf(s1));
            }
        }
    }
    if (l == 0) sden[wid * 4 + o] = accDeno;
    __syncthreads();
    if (tid == 0) {
        float sd = 0.f;
        #pragma unroll
        for (int i = 0; i < 16; ++i) sd += sden[i];
        g_deno[blockIdx.x] = sd;
    }
}

__global__ __launch_bounds__(256) void finalize_kernel(float* __restrict__ out)
{
    __shared__ float sd[256], sn[256];
    const int t = threadIdx.x;
    sd[t] = g_deno[t] + g_deno[t + 256] + g_deno[t + 512] + g_deno[t + 768];
    sn[t] = g_nll[t]  + g_nll[t + 256];
    __syncthreads();
    for (int ofs = 128; ofs > 0; ofs >>= 1) {
        if (t < ofs) { sd[t] += sd[t + ofs]; sn[t] += sn[t + ofs]; }
        __syncthreads();
    }
    if (t == 0) {
        const float invB = 1.0f / (float)BATCH;
        float deno = fminf(fmaxf(sd[0] * invB, 1e-5f), 10.f);
        float cono = fminf(fmaxf(sn[0] * invB, 1e-5f), 10.f);
        out[0] = fmaxf(deno + cono, 1e-5f);
        out[1] = deno;
        out[2] = cono;
    }
}

extern "C" void kernel_launch(void* const* d_in, const int* in_sizes, int n_in,
                              void* d_out, int out_size)
{
    const int*   cen_ids = (const int*)  d_in[0];
    const int*   ctx_ids = (const int*)  d_in[1];
    const int*   neg_ids = (const int*)  d_in[2];
    const int*   labels  = (const int*)  d_in[3];
    const float* cen_emb = (const float*)d_in[4];
    const float* ctx_emb = (const float*)d_in[5];
    const float* W_enc   = (const float*)d_in[6];
    const float* b_enc   = (const float*)d_in[7];
    const float* W_dec   = (const float*)d_in[8];
    const float* b_dec   = (const float*)d_in[9];
    const float* W_cls   = (const float*)d_in[10];
    const float* b_cls   = (const float*)d_in[11];

    __nv_bfloat16* we;  cudaGetSymbolAddress((void**)&we, g_Wenc);
    __nv_bfloat16* wd;  cudaGetSymbolAddress((void**)&wd, g_Wdec);

    const int cBlocks = (KPAD * KPAD + 255) / 256;
    convert_w<<<cBlocks, 256>>>(we, W_enc);
    convert_w<<<cBlocks, 256>>>(wd, W_dec);

    cudaFuncSetAttribute(hetero_kernel,
                         cudaFuncAttributeMaxDynamicSharedMemorySize, SM_TOTAL);
    hetero_kernel<<<GRID, THREADS, SM_TOTAL>>>(
        cen_ids, labels, cen_emb, ctx_emb, b_enc, b_dec, W_cls, b_cls);
    dot_kernel<<<1024, 128>>>(ctx_ids, neg_ids);
    finalize_kernel<<<1, 256>>>((float*)d_out);
}